// round 2
// baseline (speedup 1.0000x reference)
#include <cuda_runtime.h>
#include <cstdint>

#define DD 128
#define NMAX 100000
#define NGRAPH 64

// Scratch (no allocation allowed -> __device__ globals)
__device__ float g_H [(size_t)NMAX * DD];
__device__ float g_A0[(size_t)NMAX * DD];
__device__ float g_A1[(size_t)NMAX * DD];
__device__ int   g_MAX[NGRAPH * DD];

// ---------- packed fp32x2 helpers (sm_103a FFMA2 path, exact fp32 math) ----------
__device__ __forceinline__ unsigned long long pack2(float a) {
    unsigned long long r;
    asm("mov.b64 %0, {%1, %1};" : "=l"(r) : "f"(a));
    return r;
}
__device__ __forceinline__ void fma2(unsigned long long& acc, unsigned long long a,
                                     unsigned long long b) {
    asm("fma.rn.f32x2 %0, %1, %2, %0;" : "+l"(acc) : "l"(a), "l"(b));
}
__device__ __forceinline__ float2 unpack2(unsigned long long v) {
    float2 f;
    asm("mov.b64 {%0, %1}, %2;" : "=f"(f.x), "=f"(f.y) : "l"(v));
    return f;
}

// ---------- monotonic float<->int encoding for atomicMax over signed floats ----------
__device__ __forceinline__ int encf(float f) {
    int i = __float_as_int(f);
    return i >= 0 ? i : (i ^ 0x7fffffff);
}
__device__ __forceinline__ float decf(int i) {
    return __int_as_float(i >= 0 ? i : (i ^ 0x7fffffff));
}

// ---------- kernels ----------

// agg0 = x  (only needed for layer 0; later layers get agg written by the MLP epilogue)
__global__ void copy_kernel(const float4* __restrict__ in, float4* __restrict__ out, int n4) {
    int i = blockIdx.x * blockDim.x + threadIdx.x;
    if (i < n4) out[i] = in[i];
}

// One warp per TWO edges: each lane covers 2 independent float4 gathers + 2 red.v4,
// doubling per-thread MLP vs the 1-edge/warp version.
__global__ void scatter_kernel(const float4* __restrict__ h, float4* __restrict__ agg,
                               const int* __restrict__ src, const int* __restrict__ dst,
                               int nE) {
    int w = (int)(((unsigned)blockIdx.x * blockDim.x + threadIdx.x) >> 5);
    int lane = threadIdx.x & 31;
    int half = lane >> 4;            // 0 or 1: which of the 2 edges base
    int q    = lane & 15;            // float4 index within a half-row (16 x 16B = 256B)
    int e0 = w * 2;
    if (e0 >= nE) return;

    // edge A: lanes 0-15 cover f4[0..15], lanes 16-31 cover f4[16..31] of edge e0? No —
    // simpler: each lane handles f4 slot (half*16+q) of edge e0 AND edge e0+1.
    int slot = half * 16 + q;        // 0..31, full 512B row across the warp
    int sA = __ldg(src + e0);
    int dA = __ldg(dst + e0);
    float4 vA = __ldg(h + (size_t)sA * 32 + slot);

    bool hasB = (e0 + 1) < nE;
    int sB = hasB ? __ldg(src + e0 + 1) : sA;
    int dB = hasB ? __ldg(dst + e0 + 1) : dA;
    float4 vB = __ldg(h + (size_t)sB * 32 + slot);   // independent load, overlaps vA

    float4* pA = agg + (size_t)dA * 32 + slot;
    asm volatile("red.global.add.v4.f32 [%0], {%1, %2, %3, %4};"
                 :: "l"(pA), "f"(vA.x), "f"(vA.y), "f"(vA.z), "f"(vA.w)
                 : "memory");
    if (hasB) {
        float4* pB = agg + (size_t)dB * 32 + slot;
        asm volatile("red.global.add.v4.f32 [%0], {%1, %2, %3, %4};"
                     :: "l"(pB), "f"(vB.x), "f"(vB.y), "f"(vB.z), "f"(vB.w)
                     : "memory");
    }
}

// Fused MLP: out = [relu]( relu(A @ W1 + b1) @ W2 + b2 ); writes Hout and optionally AggOut.
// Block: 256 threads, 64 rows x 128 cols. Thread computes 4 rows x 8 cols via f32x2 FMAs.
__global__ __launch_bounds__(256) void mlp_kernel(
    const float* __restrict__ A,
    const float* __restrict__ W1, const float* __restrict__ b1,
    const float* __restrict__ W2, const float* __restrict__ b2,
    float* __restrict__ Hout, float* __restrict__ AggOut,
    int n, int reluOut)
{
    __shared__ __align__(16) float  sT[64][132];  // input tile, then intermediate tile
    __shared__ __align__(16) float4 sW[16][32];   // 16 x 128 weight chunk

    int tid = threadIdx.x;
    int tx = tid & 15;               // col group: cols [tx*8, tx*8+8)
    int ty = tid >> 4;               // row group: rows [ty*4, ty*4+4)
    int row0 = blockIdx.x * 64;

    // load A tile (zero-pad OOB rows)
    for (int i = tid; i < 2048; i += 256) {
        int r = i >> 5, c = i & 31;
        float4 v = make_float4(0.f, 0.f, 0.f, 0.f);
        if (row0 + r < n) v = __ldg((const float4*)A + (size_t)(row0 + r) * 32 + c);
        *(float4*)&sT[r][c * 4] = v;
    }

    unsigned long long acc[4][4];

    // ---- GEMM1: inter = A @ W1 ----
    #pragma unroll
    for (int i = 0; i < 4; i++)
        #pragma unroll
        for (int j = 0; j < 4; j++) acc[i][j] = 0ull;

    for (int k0 = 0; k0 < 128; k0 += 16) {
        __syncthreads();
        for (int i2 = tid; i2 < 512; i2 += 256) {
            int kk = i2 >> 5, c = i2 & 31;
            sW[kk][c] = __ldg((const float4*)W1 + (size_t)(k0 + kk) * 32 + c);
        }
        __syncthreads();
        #pragma unroll
        for (int kk = 0; kk < 16; kk++) {
            ulonglong2 wa = *(const ulonglong2*)&sW[kk][tx * 2];
            ulonglong2 wb = *(const ulonglong2*)&sW[kk][tx * 2 + 1];
            #pragma unroll
            for (int i = 0; i < 4; i++) {
                unsigned long long ap = pack2(sT[ty * 4 + i][k0 + kk]);
                fma2(acc[i][0], ap, wa.x);
                fma2(acc[i][1], ap, wa.y);
                fma2(acc[i][2], ap, wb.x);
                fma2(acc[i][3], ap, wb.y);
            }
        }
    }
    __syncthreads();  // everyone done reading sT before we overwrite it

    // bias + relu -> write intermediate into sT
    {
        float4 bb0 = __ldg((const float4*)b1 + tx * 2);
        float4 bb1 = __ldg((const float4*)b1 + tx * 2 + 1);
        #pragma unroll
        for (int i = 0; i < 4; i++) {
            float2 f0 = unpack2(acc[i][0]);
            float2 f1 = unpack2(acc[i][1]);
            float2 f2 = unpack2(acc[i][2]);
            float2 f3 = unpack2(acc[i][3]);
            float4 o0 = make_float4(fmaxf(f0.x + bb0.x, 0.f), fmaxf(f0.y + bb0.y, 0.f),
                                    fmaxf(f1.x + bb0.z, 0.f), fmaxf(f1.y + bb0.w, 0.f));
            float4 o1 = make_float4(fmaxf(f2.x + bb1.x, 0.f), fmaxf(f2.y + bb1.y, 0.f),
                                    fmaxf(f3.x + bb1.z, 0.f), fmaxf(f3.y + bb1.w, 0.f));
            *(float4*)&sT[ty * 4 + i][tx * 8]     = o0;
            *(float4*)&sT[ty * 4 + i][tx * 8 + 4] = o1;
        }
    }

    // ---- GEMM2: out = inter @ W2 ----
    #pragma unroll
    for (int i = 0; i < 4; i++)
        #pragma unroll
        for (int j = 0; j < 4; j++) acc[i][j] = 0ull;

    for (int k0 = 0; k0 < 128; k0 += 16) {
        __syncthreads();  // also orders the sT intermediate writes above
        for (int i2 = tid; i2 < 512; i2 += 256) {
            int kk = i2 >> 5, c = i2 & 31;
            sW[kk][c] = __ldg((const float4*)W2 + (size_t)(k0 + kk) * 32 + c);
        }
        __syncthreads();
        #pragma unroll
        for (int kk = 0; kk < 16; kk++) {
            ulonglong2 wa = *(const ulonglong2*)&sW[kk][tx * 2];
            ulonglong2 wb = *(const ulonglong2*)&sW[kk][tx * 2 + 1];
            #pragma unroll
            for (int i = 0; i < 4; i++) {
                unsigned long long ap = pack2(sT[ty * 4 + i][k0 + kk]);
                fma2(acc[i][0], ap, wa.x);
                fma2(acc[i][1], ap, wa.y);
                fma2(acc[i][2], ap, wb.x);
                fma2(acc[i][3], ap, wb.y);
            }
        }
    }

    // epilogue: bias (+ optional relu), write Hout (and AggOut = next layer's agg init)
    {
        float4 bb0 = __ldg((const float4*)b2 + tx * 2);
        float4 bb1 = __ldg((const float4*)b2 + tx * 2 + 1);
        #pragma unroll
        for (int i = 0; i < 4; i++) {
            int row = row0 + ty * 4 + i;
            if (row >= n) continue;
            float2 f0 = unpack2(acc[i][0]);
            float2 f1 = unpack2(acc[i][1]);
            float2 f2 = unpack2(acc[i][2]);
            float2 f3 = unpack2(acc[i][3]);
            float4 o0 = make_float4(f0.x + bb0.x, f0.y + bb0.y, f1.x + bb0.z, f1.y + bb0.w);
            float4 o1 = make_float4(f2.x + bb1.x, f2.y + bb1.y, f3.x + bb1.z, f3.y + bb1.w);
            if (reluOut) {
                o0.x = fmaxf(o0.x, 0.f); o0.y = fmaxf(o0.y, 0.f);
                o0.z = fmaxf(o0.z, 0.f); o0.w = fmaxf(o0.w, 0.f);
                o1.x = fmaxf(o1.x, 0.f); o1.y = fmaxf(o1.y, 0.f);
                o1.z = fmaxf(o1.z, 0.f); o1.w = fmaxf(o1.w, 0.f);
            }
            size_t off = (size_t)row * 32 + tx * 2;
            ((float4*)Hout)[off]     = o0;
            ((float4*)Hout)[off + 1] = o1;
            if (AggOut) {
                ((float4*)AggOut)[off]     = o0;
                ((float4*)AggOut)[off + 1] = o1;
            }
        }
    }
}

__global__ void initmax_kernel() {
    int i = blockIdx.x * blockDim.x + threadIdx.x;
    if (i < NGRAPH * DD) g_MAX[i] = (int)0x807fffff;  // enc(-inf)
}

// batch is sorted: per-thread running max over a contiguous node chunk, flush on boundary.
__global__ void maxpool_kernel(const float* __restrict__ h, const int* __restrict__ batch,
                               int n) {
    __shared__ int sb[512];
    int c = threadIdx.x;  // 0..127 (one column per thread)
    int start = blockIdx.x * 512;
    if (start >= n) return;
    int cnt = min(512, n - start);
    for (int i = c; i < cnt; i += 128) sb[i] = __ldg(batch + start + i);
    __syncthreads();

    int cur = sb[0];
    float m = __int_as_float(0xff800000);  // -inf
    for (int r = 0; r < cnt; ++r) {
        int b = sb[r];
        if (b != cur) {
            atomicMax(&g_MAX[cur * DD + c], encf(m));
            cur = b;
            m = __int_as_float(0xff800000);
        }
        m = fmaxf(m, __ldg(h + (size_t)(start + r) * DD + c));
    }
    atomicMax(&g_MAX[cur * DD + c], encf(m));
}

__global__ void decode_kernel(float* __restrict__ out) {
    int i = blockIdx.x * blockDim.x + threadIdx.x;
    if (i < NGRAPH * DD) out[i] = decf(g_MAX[i]);
}

// ---------- launch ----------
extern "C" void kernel_launch(void* const* d_in, const int* in_sizes, int n_in,
                              void* d_out, int out_size) {
    const float* x     = (const float*)d_in[0];
    const int*   ei    = (const int*)  d_in[1];
    const int*   batch = (const int*)  d_in[2];
    const float* W1    = (const float*)d_in[3];
    const float* b1    = (const float*)d_in[4];
    const float* W2    = (const float*)d_in[5];
    const float* b2    = (const float*)d_in[6];
    float* out = (float*)d_out;

    int n  = in_sizes[2];
    int nE = in_sizes[1] / 2;
    const int* src = ei;
    const int* dst = ei + nE;

    float *H, *A0, *A1;
    cudaGetSymbolAddress((void**)&H,  g_H);
    cudaGetSymbolAddress((void**)&A0, g_A0);
    cudaGetSymbolAddress((void**)&A1, g_A1);
    float* Abuf[2] = {A0, A1};

    int n4 = n * 32;
    copy_kernel<<<(n4 + 255) / 256, 256>>>((const float4*)x, (float4*)A0, n4);

    const float* hcur = x;
    int nblk = (n + 63) / 64;
    int nWarps = (nE + 1) / 2;                     // 2 edges per warp
    int nBlocksScatter = (nWarps + 7) / 8;         // 8 warps per block
    for (int l = 0; l < 3; ++l) {
        scatter_kernel<<<nBlocksScatter, 256>>>((const float4*)hcur, (float4*)Abuf[l & 1],
                                                src, dst, nE);
        int last = (l == 2);
        mlp_kernel<<<nblk, 256>>>(Abuf[l & 1],
                                  W1 + (size_t)l * DD * DD, b1 + (size_t)l * DD,
                                  W2 + (size_t)l * DD * DD, b2 + (size_t)l * DD,
                                  H, last ? nullptr : Abuf[(l + 1) & 1],
                                  n, last ? 0 : 1);
        hcur = H;
    }

    initmax_kernel<<<(NGRAPH * DD + 255) / 256, 256>>>();
    maxpool_kernel<<<(n + 511) / 512, 128>>>(H, batch, n);
    decode_kernel<<<(NGRAPH * DD + 255) / 256, 256>>>(out);
}

// round 4
// speedup vs baseline: 1.7713x; 1.7713x over previous
#include <cuda_runtime.h>
#include <cstdint>

#define DD 128
#define NMAX 100000
#define NEMAX 1600000
#define NGRAPH 64
#define ROWW 132              // padded row stride (words) for 128-wide tiles, 16B-aligned

// Scratch (no allocation allowed -> __device__ globals)
__device__ float g_H[(size_t)NMAX * DD];
__device__ float g_A[(size_t)NMAX * DD];
__device__ int   g_deg[NMAX];
__device__ int   g_cnt[NMAX];
__device__ int   g_rowptr[NMAX + 1];
__device__ int   g_part[512];
__device__ int   g_ssrc[NEMAX];
__device__ int   g_MAX[NGRAPH * DD];

// ---------- packed fp32x2 helpers (sm_103a FFMA2 path, exact fp32 math) ----------
__device__ __forceinline__ unsigned long long pack2(float a) {
    unsigned long long r;
    asm("mov.b64 %0, {%1, %1};" : "=l"(r) : "f"(a));
    return r;
}
__device__ __forceinline__ void fma2(unsigned long long& acc, unsigned long long a,
                                     unsigned long long b) {
    asm("fma.rn.f32x2 %0, %1, %2, %0;" : "+l"(acc) : "l"(a), "l"(b));
}
__device__ __forceinline__ float2 unpack2(unsigned long long v) {
    float2 f;
    asm("mov.b64 {%0, %1}, %2;" : "=f"(f.x), "=f"(f.y) : "l"(v));
    return f;
}

// ---------- monotonic float<->int encoding for atomicMax over signed floats ----------
__device__ __forceinline__ int encf(float f) {
    int i = __float_as_int(f);
    return i >= 0 ? i : (i ^ 0x7fffffff);
}
__device__ __forceinline__ float decf(int i) {
    return __int_as_float(i >= 0 ? i : (i ^ 0x7fffffff));
}

// ================= CSR build (once per launch; edges constant across layers) ========

__global__ void zero_kernel(int n) {
    int i = blockIdx.x * blockDim.x + threadIdx.x;
    if (i < n) { g_deg[i] = 0; g_cnt[i] = 0; }
}

__global__ void hist_kernel(const int* __restrict__ dst, int nE) {
    int e = blockIdx.x * blockDim.x + threadIdx.x;
    if (e < nE) atomicAdd(&g_deg[__ldg(dst + e)], 1);
}

// per-block exclusive scan of deg -> rowptr; block sums -> part
__global__ void scan1_kernel(int n) {
    __shared__ int s[512];
    int tid = threadIdx.x;
    int i = blockIdx.x * 512 + tid;
    int v = (i < n) ? g_deg[i] : 0;
    s[tid] = v;
    __syncthreads();
    #pragma unroll
    for (int off = 1; off < 512; off <<= 1) {
        int t = (tid >= off) ? s[tid - off] : 0;
        __syncthreads();
        s[tid] += t;
        __syncthreads();
    }
    if (i < n) g_rowptr[i] = s[tid] - v;       // exclusive
    if (tid == 511) g_part[blockIdx.x] = s[511];
}

// single block: exclusive scan over block sums (nb <= 512)
__global__ void scan2_kernel(int nb) {
    __shared__ int s[512];
    int tid = threadIdx.x;
    int v = (tid < nb) ? g_part[tid] : 0;
    s[tid] = v;
    __syncthreads();
    #pragma unroll
    for (int off = 1; off < 512; off <<= 1) {
        int t = (tid >= off) ? s[tid - off] : 0;
        __syncthreads();
        s[tid] += t;
        __syncthreads();
    }
    if (tid < nb) g_part[tid] = s[tid] - v;
}

__global__ void scan3_kernel(int n, int nE) {
    int i = blockIdx.x * 512 + threadIdx.x;
    if (i < n) g_rowptr[i] += g_part[blockIdx.x];
    if (i == 0) g_rowptr[n] = nE;
}

__global__ void fill_kernel(const int* __restrict__ src, const int* __restrict__ dst, int nE) {
    int e = blockIdx.x * blockDim.x + threadIdx.x;
    if (e >= nE) return;
    int d = __ldg(dst + e);
    int pos = g_rowptr[d] + atomicAdd(&g_cnt[d], 1);
    g_ssrc[pos] = __ldg(src + e);
}

// ================= gather: agg[i] = h[i] + sum_{j in neigh(i)} h[j] ================
// warp per node, lane per float4 slot (32 x 16B = 512B row); 4 edges in flight.
__global__ void gather_kernel(const float4* __restrict__ h, float4* __restrict__ agg, int n) {
    int node = (int)(((unsigned)blockIdx.x * blockDim.x + threadIdx.x) >> 5);
    if (node >= n) return;
    int lane = threadIdx.x & 31;
    int beg = __ldg(g_rowptr + node);
    int end = __ldg(g_rowptr + node + 1);
    float4 acc = __ldg(h + (size_t)node * 32 + lane);   // self term (eps=0)
    int e = beg;
    for (; e + 3 < end; e += 4) {
        int s0 = __ldg(g_ssrc + e);
        int s1 = __ldg(g_ssrc + e + 1);
        int s2 = __ldg(g_ssrc + e + 2);
        int s3 = __ldg(g_ssrc + e + 3);
        float4 v0 = __ldg(h + (size_t)s0 * 32 + lane);
        float4 v1 = __ldg(h + (size_t)s1 * 32 + lane);
        float4 v2 = __ldg(h + (size_t)s2 * 32 + lane);
        float4 v3 = __ldg(h + (size_t)s3 * 32 + lane);
        acc.x += (v0.x + v1.x) + (v2.x + v3.x);
        acc.y += (v0.y + v1.y) + (v2.y + v3.y);
        acc.z += (v0.z + v1.z) + (v2.z + v3.z);
        acc.w += (v0.w + v1.w) + (v2.w + v3.w);
    }
    for (; e < end; ++e) {
        int s0 = __ldg(g_ssrc + e);
        float4 v0 = __ldg(h + (size_t)s0 * 32 + lane);
        acc.x += v0.x; acc.y += v0.y; acc.z += v0.z; acc.w += v0.w;
    }
    agg[(size_t)node * 32 + lane] = acc;
}

// ================= fused MLP, 128x128 tile, 8x8 per-thread regs, FFMA2 ==============

__device__ __forceinline__ void gemm128(const float* __restrict__ Wg,
                                        const float* __restrict__ sBig,
                                        float* __restrict__ sW,
                                        unsigned long long (&acc)[8][4],
                                        int tid, int r0, int tx)
{
    #pragma unroll
    for (int i = 0; i < 8; i++)
        #pragma unroll
        for (int q = 0; q < 4; q++) acc[i][q] = 0ull;

    for (int k0 = 0; k0 < 128; k0 += 16) {
        __syncthreads();   // previous users of sW done (also orders sBig producer writes)
        #pragma unroll
        for (int t = 0; t < 2; t++) {
            int idx = tid + t * 256;
            int kk = idx >> 5, c4 = idx & 31;
            *(float4*)&sW[kk * 128 + c4 * 4] =
                __ldg((const float4*)Wg + (size_t)(k0 + kk) * 32 + c4);
        }
        __syncthreads();
        #pragma unroll
        for (int kk2 = 0; kk2 < 8; kk2++) {
            float2 a2[8];
            #pragma unroll
            for (int i = 0; i < 8; i++)
                a2[i] = *(const float2*)&sBig[(r0 + i) * ROWW + k0 + kk2 * 2];
            #pragma unroll
            for (int j = 0; j < 2; j++) {
                int kk = kk2 * 2 + j;
                ulonglong2 wa = *(const ulonglong2*)&sW[kk * 128 + tx * 8];
                ulonglong2 wb = *(const ulonglong2*)&sW[kk * 128 + tx * 8 + 4];
                #pragma unroll
                for (int i = 0; i < 8; i++) {
                    unsigned long long ap = pack2(j == 0 ? a2[i].x : a2[i].y);
                    fma2(acc[i][0], ap, wa.x);
                    fma2(acc[i][1], ap, wa.y);
                    fma2(acc[i][2], ap, wb.x);
                    fma2(acc[i][3], ap, wb.y);
                }
            }
        }
    }
}

__global__ __launch_bounds__(256, 2) void mlp_kernel(
    const float* __restrict__ A,
    const float* __restrict__ W1, const float* __restrict__ b1,
    const float* __restrict__ W2, const float* __restrict__ b2,
    float* __restrict__ Hout, int n, int reluOut)
{
    extern __shared__ float sm[];
    float* sBig = sm;                 // [128][ROWW]: A tile, then intermediate tile
    float* sW   = sm + 128 * ROWW;    // [16][128] weight chunk

    int tid = threadIdx.x;
    int tx = tid & 15, ty = tid >> 4;
    int r0 = ty * 8, c0 = tx * 8;
    int row0 = blockIdx.x * 128;

    // load A tile (zero-pad OOB rows)
    for (int idx = tid; idx < 128 * 32; idx += 256) {
        int r = idx >> 5, c4 = idx & 31;
        float4 v = make_float4(0.f, 0.f, 0.f, 0.f);
        if (row0 + r < n) v = __ldg((const float4*)A + (size_t)(row0 + r) * 32 + c4);
        *(float4*)&sBig[r * ROWW + c4 * 4] = v;
    }
    // (first sync inside gemm128 orders these stores before compute)

    unsigned long long acc[8][4];
    gemm128(W1, sBig, sW, acc, tid, r0, tx);

    __syncthreads();   // all GEMM1 reads of sBig(A) done before we overwrite with inter
    {
        float4 bb0 = __ldg((const float4*)b1 + tx * 2);
        float4 bb1 = __ldg((const float4*)b1 + tx * 2 + 1);
        #pragma unroll
        for (int i = 0; i < 8; i++) {
            float2 f0 = unpack2(acc[i][0]);
            float2 f1 = unpack2(acc[i][1]);
            float2 f2 = unpack2(acc[i][2]);
            float2 f3 = unpack2(acc[i][3]);
            float4 o0 = make_float4(fmaxf(f0.x + bb0.x, 0.f), fmaxf(f0.y + bb0.y, 0.f),
                                    fmaxf(f1.x + bb0.z, 0.f), fmaxf(f1.y + bb0.w, 0.f));
            float4 o1 = make_float4(fmaxf(f2.x + bb1.x, 0.f), fmaxf(f2.y + bb1.y, 0.f),
                                    fmaxf(f3.x + bb1.z, 0.f), fmaxf(f3.y + bb1.w, 0.f));
            *(float4*)&sBig[(r0 + i) * ROWW + c0]     = o0;
            *(float4*)&sBig[(r0 + i) * ROWW + c0 + 4] = o1;
        }
    }
    // gemm2's first sync orders inter stores before compute
    gemm128(W2, sBig, sW, acc, tid, r0, tx);

    {
        float4 bb0 = __ldg((const float4*)b2 + tx * 2);
        float4 bb1 = __ldg((const float4*)b2 + tx * 2 + 1);
        #pragma unroll
        for (int i = 0; i < 8; i++) {
            int row = row0 + r0 + i;
            if (row >= n) continue;
            float2 f0 = unpack2(acc[i][0]);
            float2 f1 = unpack2(acc[i][1]);
            float2 f2 = unpack2(acc[i][2]);
            float2 f3 = unpack2(acc[i][3]);
            float4 o0 = make_float4(f0.x + bb0.x, f0.y + bb0.y, f1.x + bb0.z, f1.y + bb0.w);
            float4 o1 = make_float4(f2.x + bb1.x, f2.y + bb1.y, f3.x + bb1.z, f3.y + bb1.w);
            if (reluOut) {
                o0.x = fmaxf(o0.x, 0.f); o0.y = fmaxf(o0.y, 0.f);
                o0.z = fmaxf(o0.z, 0.f); o0.w = fmaxf(o0.w, 0.f);
                o1.x = fmaxf(o1.x, 0.f); o1.y = fmaxf(o1.y, 0.f);
                o1.z = fmaxf(o1.z, 0.f); o1.w = fmaxf(o1.w, 0.f);
            }
            size_t off = (size_t)row * 32 + tx * 2;
            ((float4*)Hout)[off]     = o0;
            ((float4*)Hout)[off + 1] = o1;
        }
    }
}

// ================= pooling =========================================================

__global__ void initmax_kernel() {
    int i = blockIdx.x * blockDim.x + threadIdx.x;
    if (i < NGRAPH * DD) g_MAX[i] = (int)0x807fffff;  // enc(-inf)
}

__global__ void maxpool_kernel(const float* __restrict__ h, const int* __restrict__ batch,
                               int n) {
    __shared__ int sb[512];
    int c = threadIdx.x;  // 0..127
    int start = blockIdx.x * 512;
    if (start >= n) return;
    int cnt = min(512, n - start);
    for (int i = c; i < cnt; i += 128) sb[i] = __ldg(batch + start + i);
    __syncthreads();

    int cur = sb[0];
    float m = __int_as_float(0xff800000);
    for (int r = 0; r < cnt; ++r) {
        int b = sb[r];
        if (b != cur) {
            atomicMax(&g_MAX[cur * DD + c], encf(m));
            cur = b;
            m = __int_as_float(0xff800000);
        }
        m = fmaxf(m, __ldg(h + (size_t)(start + r) * DD + c));
    }
    atomicMax(&g_MAX[cur * DD + c], encf(m));
}

__global__ void decode_kernel(float* __restrict__ out) {
    int i = blockIdx.x * blockDim.x + threadIdx.x;
    if (i < NGRAPH * DD) out[i] = decf(g_MAX[i]);
}

// ================= launch ==========================================================

extern "C" void kernel_launch(void* const* d_in, const int* in_sizes, int n_in,
                              void* d_out, int out_size) {
    const float* x     = (const float*)d_in[0];
    const int*   ei    = (const int*)  d_in[1];
    const int*   batch = (const int*)  d_in[2];
    const float* W1    = (const float*)d_in[3];
    const float* b1    = (const float*)d_in[4];
    const float* W2    = (const float*)d_in[5];
    const float* b2    = (const float*)d_in[6];
    float* out = (float*)d_out;

    int n  = in_sizes[2];
    int nE = in_sizes[1] / 2;
    const int* src = ei;
    const int* dst = ei + nE;

    float *H, *A;
    cudaGetSymbolAddress((void**)&H, g_H);
    cudaGetSymbolAddress((void**)&A, g_A);

    const int SMEMB = (128 * ROWW + 16 * 128) * sizeof(float);  // 75776 B
    cudaFuncSetAttribute(mlp_kernel, cudaFuncAttributeMaxDynamicSharedMemorySize, SMEMB);

    // ---- CSR build (deterministic up to within-bucket order) ----
    zero_kernel<<<(n + 255) / 256, 256>>>(n);
    hist_kernel<<<(nE + 255) / 256, 256>>>(dst, nE);
    int nb = (n + 511) / 512;
    scan1_kernel<<<nb, 512>>>(n);
    scan2_kernel<<<1, 512>>>(nb);
    scan3_kernel<<<nb, 512>>>(n, nE);
    fill_kernel<<<(nE + 255) / 256, 256>>>(src, dst, nE);

    // ---- 3 GIN layers ----
    const float* hcur = x;
    int gblk = (n + 7) / 8;       // warp per node, 8 nodes per 256-thread block
    int mblk = (n + 127) / 128;
    for (int l = 0; l < 3; ++l) {
        gather_kernel<<<gblk, 256>>>((const float4*)hcur, (float4*)A, n);
        int last = (l == 2);
        mlp_kernel<<<mblk, 256, SMEMB>>>(A,
                                         W1 + (size_t)l * DD * DD, b1 + (size_t)l * DD,
                                         W2 + (size_t)l * DD * DD, b2 + (size_t)l * DD,
                                         H, n, last ? 0 : 1);
        hcur = H;
    }

    initmax_kernel<<<(NGRAPH * DD + 255) / 256, 256>>>();
    maxpool_kernel<<<(n + 511) / 512, 128>>>(H, batch, n);
    decode_kernel<<<(NGRAPH * DD + 255) / 256, 256>>>(out);
}

// round 12
// speedup vs baseline: 2.2364x; 1.2626x over previous
#include <cuda_runtime.h>
#include <cstdint>

#define DD 128
#define NMAX 100000
#define NEMAX 1600000
#define NGRAPH 64
#define ROWW 132          // fp32 A/inter tile row stride (words)
#define WSTR 132          // W chunk row stride (words)
#define MLP_SMEM ((128 * ROWW + 16 * WSTR) * 4)   // 76032 B

// Scratch (no allocation allowed -> __device__ globals)
__device__ float g_H[(size_t)NMAX * DD];
__device__ float g_A[(size_t)NMAX * DD];
__device__ int   g_deg[NMAX];
__device__ int   g_cnt[NMAX];
__device__ int   g_rowptr[NMAX + 1];
__device__ int   g_part[512];
__device__ int   g_ssrc[NEMAX];
__device__ int   g_MAX[NGRAPH * DD];

// ---------- monotonic float<->int encoding for atomicMax over signed floats ----------
__device__ __forceinline__ int encf(float f) {
    int i = __float_as_int(f);
    return i >= 0 ? i : (i ^ 0x7fffffff);
}
__device__ __forceinline__ float decf(int i) {
    return __int_as_float(i >= 0 ? i : (i ^ 0x7fffffff));
}

// ---------- tf32 helpers (standard PTX, supported on compute_103 base) ----------
__device__ __forceinline__ uint32_t f2tf32(float f) {
    uint32_t r;
    asm("cvt.rna.tf32.f32 %0, %1;" : "=r"(r) : "f"(f));
    return r;
}
// D += A(16x8) * B(8x8), tf32 inputs, fp32 accumulate (sm_80+ mma.sync)
__device__ __forceinline__ void mma_tf32(float (&c)[4],
                                         uint32_t a0, uint32_t a1, uint32_t a2, uint32_t a3,
                                         uint32_t b0, uint32_t b1) {
    asm("mma.sync.aligned.m16n8k8.row.col.f32.tf32.tf32.f32 "
        "{%0,%1,%2,%3}, {%4,%5,%6,%7}, {%8,%9}, {%0,%1,%2,%3};"
        : "+f"(c[0]), "+f"(c[1]), "+f"(c[2]), "+f"(c[3])
        : "r"(a0), "r"(a1), "r"(a2), "r"(a3), "r"(b0), "r"(b1));
}

// ================= CSR build (once per launch; edges constant across layers) ========

__global__ void zero_kernel(int n) {
    int i = blockIdx.x * blockDim.x + threadIdx.x;
    if (i < n) { g_deg[i] = 0; g_cnt[i] = 0; }
}
__global__ void hist_kernel(const int* __restrict__ dst, int nE) {
    int e = blockIdx.x * blockDim.x + threadIdx.x;
    if (e < nE) atomicAdd(&g_deg[__ldg(dst + e)], 1);
}
__global__ void scan1_kernel(int n) {
    __shared__ int s[512];
    int tid = threadIdx.x;
    int i = blockIdx.x * 512 + tid;
    int v = (i < n) ? g_deg[i] : 0;
    s[tid] = v;
    __syncthreads();
    #pragma unroll
    for (int off = 1; off < 512; off <<= 1) {
        int t = (tid >= off) ? s[tid - off] : 0;
        __syncthreads();
        s[tid] += t;
        __syncthreads();
    }
    if (i < n) g_rowptr[i] = s[tid] - v;
    if (tid == 511) g_part[blockIdx.x] = s[511];
}
__global__ void scan2_kernel(int nb) {
    __shared__ int s[512];
    int tid = threadIdx.x;
    int v = (tid < nb) ? g_part[tid] : 0;
    s[tid] = v;
    __syncthreads();
    #pragma unroll
    for (int off = 1; off < 512; off <<= 1) {
        int t = (tid >= off) ? s[tid - off] : 0;
        __syncthreads();
        s[tid] += t;
        __syncthreads();
    }
    if (tid < nb) g_part[tid] = s[tid] - v;
}
__global__ void scan3_kernel(int n, int nE) {
    int i = blockIdx.x * 512 + threadIdx.x;
    if (i < n) g_rowptr[i] += g_part[blockIdx.x];
    if (i == 0) g_rowptr[n] = nE;
}
__global__ void fill_kernel(const int* __restrict__ src, const int* __restrict__ dst, int nE) {
    int e = blockIdx.x * blockDim.x + threadIdx.x;
    if (e >= nE) return;
    int d = __ldg(dst + e);
    int pos = g_rowptr[d] + atomicAdd(&g_cnt[d], 1);
    g_ssrc[pos] = __ldg(src + e);
}

// ================= gather: agg[i] = h[i] + sum_{j in neigh(i)} h[j] ================

__global__ void gather_kernel(const float4* __restrict__ h, float4* __restrict__ agg, int n) {
    int node = (int)(((unsigned)blockIdx.x * blockDim.x + threadIdx.x) >> 5);
    if (node >= n) return;
    int lane = threadIdx.x & 31;
    int beg = __ldg(g_rowptr + node);
    int end = __ldg(g_rowptr + node + 1);
    float4 acc = __ldg(h + (size_t)node * 32 + lane);
    int e = beg;
    for (; e + 3 < end; e += 4) {
        int s0 = __ldg(g_ssrc + e);
        int s1 = __ldg(g_ssrc + e + 1);
        int s2 = __ldg(g_ssrc + e + 2);
        int s3 = __ldg(g_ssrc + e + 3);
        float4 v0 = __ldg(h + (size_t)s0 * 32 + lane);
        float4 v1 = __ldg(h + (size_t)s1 * 32 + lane);
        float4 v2 = __ldg(h + (size_t)s2 * 32 + lane);
        float4 v3 = __ldg(h + (size_t)s3 * 32 + lane);
        acc.x += (v0.x + v1.x) + (v2.x + v3.x);
        acc.y += (v0.y + v1.y) + (v2.y + v3.y);
        acc.z += (v0.z + v1.z) + (v2.z + v3.z);
        acc.w += (v0.w + v1.w) + (v2.w + v3.w);
    }
    for (; e < end; ++e) {
        int s0 = __ldg(g_ssrc + e);
        float4 v0 = __ldg(h + (size_t)s0 * 32 + lane);
        acc.x += v0.x; acc.y += v0.y; acc.z += v0.z; acc.w += v0.w;
    }
    agg[(size_t)node * 32 + lane] = acc;
}

// ================= fused MLP via tf32 mma.sync (2-pass A-split) =====================
// CTA: 128x128 tile, 8 warps; warp tile 32 rows x 64 cols (4x2 warp grid).
// c[mf][g][q]: mf = 16-row frag (2), g = 8-col group (8), q = mma accum reg (4).

__device__ __forceinline__ void gemm_mma(const float* __restrict__ Wg,
                                         const float* __restrict__ sBig,
                                         uint32_t* __restrict__ sW,
                                         float (&c)[2][8][4],
                                         int tid, int r0, int cw0, int gid, int tig)
{
    #pragma unroll
    for (int mf = 0; mf < 2; mf++)
        #pragma unroll
        for (int g = 0; g < 8; g++)
            #pragma unroll
            for (int q = 0; q < 4; q++) c[mf][g][q] = 0.f;

    for (int k0 = 0; k0 < 128; k0 += 16) {
        __syncthreads();   // prior users of sW done (also orders sBig producer writes)
        for (int t = tid; t < 512; t += 256) {        // stage 16x128 W chunk as tf32
            int kk = t >> 5, c4 = t & 31;
            float4 v = __ldg((const float4*)Wg + (size_t)(k0 + kk) * 32 + c4);
            uint4 o = make_uint4(f2tf32(v.x), f2tf32(v.y), f2tf32(v.z), f2tf32(v.w));
            *(uint4*)&sW[kk * WSTR + c4 * 4] = o;
        }
        __syncthreads();
        #pragma unroll
        for (int kc = 0; kc < 2; kc++) {
            int kb = k0 + kc * 8;
            uint32_t ahi[2][4], alo[2][4];
            #pragma unroll
            for (int mf = 0; mf < 2; mf++) {
                int rb = r0 + mf * 16 + gid;
                float af[4];
                af[0] = sBig[(size_t)(rb    ) * ROWW + kb + tig];
                af[1] = sBig[(size_t)(rb + 8) * ROWW + kb + tig];
                af[2] = sBig[(size_t)(rb    ) * ROWW + kb + tig + 4];
                af[3] = sBig[(size_t)(rb + 8) * ROWW + kb + tig + 4];
                #pragma unroll
                for (int q = 0; q < 4; q++) {
                    ahi[mf][q] = f2tf32(af[q]);
                    alo[mf][q] = f2tf32(af[q] - __uint_as_float(ahi[mf][q]));
                }
            }
            #pragma unroll
            for (int g = 0; g < 8; g++) {
                uint32_t b0 = sW[(kc * 8 + tig    ) * WSTR + cw0 + g * 8 + gid];
                uint32_t b1 = sW[(kc * 8 + tig + 4) * WSTR + cw0 + g * 8 + gid];
                mma_tf32(c[0][g], ahi[0][0], ahi[0][1], ahi[0][2], ahi[0][3], b0, b1);
                mma_tf32(c[0][g], alo[0][0], alo[0][1], alo[0][2], alo[0][3], b0, b1);
                mma_tf32(c[1][g], ahi[1][0], ahi[1][1], ahi[1][2], ahi[1][3], b0, b1);
                mma_tf32(c[1][g], alo[1][0], alo[1][1], alo[1][2], alo[1][3], b0, b1);
            }
        }
    }
}

__global__ __launch_bounds__(256, 2) void mlp_mma_kernel(
    const float* __restrict__ A,
    const float* __restrict__ W1, const float* __restrict__ b1,
    const float* __restrict__ W2, const float* __restrict__ b2,
    float* __restrict__ Hout, int n, int reluOut)
{
    extern __shared__ float sm[];
    float*    sBig = sm;                                // [128][ROWW] fp32 A / inter
    uint32_t* sW   = (uint32_t*)(sm + 128 * ROWW);      // [16][WSTR] tf32 W chunk

    int tid  = threadIdx.x;
    int warp = tid >> 5;
    int lane = tid & 31;
    int gid  = lane >> 2;     // 0..7
    int tig  = lane & 3;      // 0..3
    int r0   = (warp & 3) * 32;
    int cw0  = (warp >> 2) * 64;
    int row0 = blockIdx.x * 128;

    // load A tile fp32 (zero-pad OOB rows); gemm's first sync orders these stores
    for (int idx = tid; idx < 128 * 32; idx += 256) {
        int r = idx >> 5, c4 = idx & 31;
        float4 v = make_float4(0.f, 0.f, 0.f, 0.f);
        if (row0 + r < n) v = __ldg((const float4*)A + (size_t)(row0 + r) * 32 + c4);
        *(float4*)&sBig[(size_t)r * ROWW + c4 * 4] = v;
    }

    float c[2][8][4];
    gemm_mma(W1, sBig, sW, c, tid, r0, cw0, gid, tig);

    __syncthreads();   // all GEMM1 reads of sBig done before overwrite with inter
    #pragma unroll
    for (int mf = 0; mf < 2; mf++) {
        int row = r0 + mf * 16 + gid;
        #pragma unroll
        for (int g = 0; g < 8; g++) {
            int col = cw0 + g * 8 + 2 * tig;
            float bv0 = __ldg(b1 + col), bv1 = __ldg(b1 + col + 1);
            float2 o0 = make_float2(fmaxf(c[mf][g][0] + bv0, 0.f),
                                    fmaxf(c[mf][g][1] + bv1, 0.f));
            float2 o1 = make_float2(fmaxf(c[mf][g][2] + bv0, 0.f),
                                    fmaxf(c[mf][g][3] + bv1, 0.f));
            *(float2*)&sBig[(size_t)(row    ) * ROWW + col] = o0;
            *(float2*)&sBig[(size_t)(row + 8) * ROWW + col] = o1;
        }
    }
    // gemm2's first sync orders the inter stores above
    gemm_mma(W2, sBig, sW, c, tid, r0, cw0, gid, tig);

    #pragma unroll
    for (int mf = 0; mf < 2; mf++) {
        int rloc = r0 + mf * 16 + gid;
        #pragma unroll
        for (int g = 0; g < 8; g++) {
            int col = cw0 + g * 8 + 2 * tig;
            float bv0 = __ldg(b2 + col), bv1 = __ldg(b2 + col + 1);
            float2 o0 = make_float2(c[mf][g][0] + bv0, c[mf][g][1] + bv1);
            float2 o1 = make_float2(c[mf][g][2] + bv0, c[mf][g][3] + bv1);
            if (reluOut) {
                o0.x = fmaxf(o0.x, 0.f); o0.y = fmaxf(o0.y, 0.f);
                o1.x = fmaxf(o1.x, 0.f); o1.y = fmaxf(o1.y, 0.f);
            }
            int rowA = row0 + rloc;
            int rowB = rowA + 8;
            if (rowA < n) *(float2*)(Hout + (size_t)rowA * 128 + col) = o0;
            if (rowB < n) *(float2*)(Hout + (size_t)rowB * 128 + col) = o1;
        }
    }
}

// ================= pooling =========================================================

__global__ void initmax_kernel() {
    int i = blockIdx.x * blockDim.x + threadIdx.x;
    if (i < NGRAPH * DD) g_MAX[i] = (int)0x807fffff;
}

__global__ void maxpool_kernel(const float* __restrict__ h, const int* __restrict__ batch,
                               int n) {
    __shared__ int sbat[512];
    int c = threadIdx.x;
    int start = blockIdx.x * 512;
    if (start >= n) return;
    int cnt = min(512, n - start);
    for (int i = c; i < cnt; i += 128) sbat[i] = __ldg(batch + start + i);
    __syncthreads();

    int cur = sbat[0];
    float m = __int_as_float(0xff800000);
    for (int r = 0; r < cnt; ++r) {
        int b = sbat[r];
        if (b != cur) {
            atomicMax(&g_MAX[cur * DD + c], encf(m));
            cur = b;
            m = __int_as_float(0xff800000);
        }
        m = fmaxf(m, __ldg(h + (size_t)(start + r) * DD + c));
    }
    atomicMax(&g_MAX[cur * DD + c], encf(m));
}

__global__ void decode_kernel(float* __restrict__ out) {
    int i = blockIdx.x * blockDim.x + threadIdx.x;
    if (i < NGRAPH * DD) out[i] = decf(g_MAX[i]);
}

// ================= launch ==========================================================

extern "C" void kernel_launch(void* const* d_in, const int* in_sizes, int n_in,
                              void* d_out, int out_size) {
    const float* x     = (const float*)d_in[0];
    const int*   ei    = (const int*)  d_in[1];
    const int*   batch = (const int*)  d_in[2];
    const float* W1    = (const float*)d_in[3];
    const float* b1    = (const float*)d_in[4];
    const float* W2    = (const float*)d_in[5];
    const float* b2    = (const float*)d_in[6];
    float* out = (float*)d_out;

    int n  = in_sizes[2];
    int nE = in_sizes[1] / 2;
    const int* src = ei;
    const int* dst = ei + nE;

    float *H, *A;
    cudaGetSymbolAddress((void**)&H, g_H);
    cudaGetSymbolAddress((void**)&A, g_A);

    cudaFuncSetAttribute(mlp_mma_kernel, cudaFuncAttributeMaxDynamicSharedMemorySize, MLP_SMEM);

    // ---- CSR build ----
    zero_kernel<<<(n + 255) / 256, 256>>>(n);
    hist_kernel<<<(nE + 255) / 256, 256>>>(dst, nE);
    int nb = (n + 511) / 512;
    scan1_kernel<<<nb, 512>>>(n);
    scan2_kernel<<<1, 512>>>(nb);
    scan3_kernel<<<nb, 512>>>(n, nE);
    fill_kernel<<<(nE + 255) / 256, 256>>>(src, dst, nE);

    // ---- 3 GIN layers ----
    const float* hcur = x;
    int gblk = (n + 7) / 8;
    int mblk = (n + 127) / 128;
    for (int l = 0; l < 3; ++l) {
        gather_kernel<<<gblk, 256>>>((const float4*)hcur, (float4*)A, n);
        int last = (l == 2);
        mlp_mma_kernel<<<mblk, 256, MLP_SMEM>>>(A,
                                                W1 + (size_t)l * DD * DD, b1 + (size_t)l * DD,
                                                W2 + (size_t)l * DD * DD, b2 + (size_t)l * DD,
                                                H, n, last ? 0 : 1);
        hcur = H;
    }

    initmax_kernel<<<(NGRAPH * DD + 255) / 256, 256>>>();
    maxpool_kernel<<<(n + 511) / 512, 128>>>(H, batch, n);
    decode_kernel<<<(NGRAPH * DD + 255) / 256, 256>>>(out);
}